// round 11
// baseline (speedup 1.0000x reference)
#include <cuda_runtime.h>
#include <cuda_fp16.h>
#include <cstdint>

#define NNODES  40000
#define FEAT    128
#define CSTRIDE 64                       // padded CSR row stride
#define CNTPAD  8                        // counter stride (ints) -> 1 per 32B sector
#define NTILES  ((NNODES + 127) / 128)   // 313 GEMM tiles
#define XSTR    136                      // smem row stride in halves (+8 pad)

// ---------------------------------------------------------------------------
// Scratch (device globals — no allocations allowed)
// ---------------------------------------------------------------------------
__device__ __half g_yh[(size_t)NNODES * FEAT];       // y = x @ W^T  fp16
__device__ int    g_cnt[(size_t)NNODES * CNTPAD];    // padded degree counters
__device__ int    g_csr[(size_t)NNODES * CSTRIDE];   // padded CSR

__device__ __forceinline__ void hmma16816(float d[4],
                                          uint32_t a0, uint32_t a1,
                                          uint32_t a2, uint32_t a3,
                                          uint32_t b0, uint32_t b1) {
    asm volatile(
        "mma.sync.aligned.m16n8k16.row.col.f32.f16.f16.f32 "
        "{%0,%1,%2,%3}, {%4,%5,%6,%7}, {%8,%9}, {%0,%1,%2,%3};"
        : "+f"(d[0]), "+f"(d[1]), "+f"(d[2]), "+f"(d[3])
        : "r"(a0), "r"(a1), "r"(a2), "r"(a3), "r"(b0), "r"(b1));
}

// ---------------------------------------------------------------------------
// K1 (fused): blocks [0, NTILES) = HMMA GEMM tile; blocks >= NTILES = build.
// ---------------------------------------------------------------------------
#define SM_XS 0
#define SM_WS (128 * XSTR * 2)
#define SM_GEMM_TOT (2 * 128 * XSTR * 2)

__global__ void __launch_bounds__(256)
sage_fused(const float* __restrict__ x,
           const float* __restrict__ W,
           const int*   __restrict__ row,
           const int*   __restrict__ col, int E) {
    if (blockIdx.x >= NTILES) {
        // ----------------- CSR build branch -----------------
        int e = (blockIdx.x - NTILES) * 256 + threadIdx.x;
        if (e >= E) return;
        int r = __ldg(&row[e]);
        int c = __ldg(&col[e]);
        int pos = atomicAdd(&g_cnt[(size_t)r * CNTPAD], 1);
        if (pos < CSTRIDE)
            g_csr[(size_t)r * CSTRIDE + pos] = c;
        return;
    }

    // ----------------- GEMM branch -----------------
    extern __shared__ char smem[];
    __half* Xs = reinterpret_cast<__half*>(smem + SM_XS);
    __half* Ws = reinterpret_cast<__half*>(smem + SM_WS);

    const int t = threadIdx.x;
    const int node0 = blockIdx.x * 128;

    const float4* W4 = reinterpret_cast<const float4*>(W);
#pragma unroll
    for (int i = 0; i < 8; i++) {
        int idx = i * 256 + t;
        int r   = idx >> 4;
        int c8  = idx & 15;

        float4 w0 = __ldg(&W4[r * 32 + 2 * c8]);
        float4 w1 = __ldg(&W4[r * 32 + 2 * c8 + 1]);
        __half2 g0 = __floats2half2_rn(w0.x, w0.y);
        __half2 g1 = __floats2half2_rn(w0.z, w0.w);
        __half2 g2 = __floats2half2_rn(w1.x, w1.y);
        __half2 g3 = __floats2half2_rn(w1.z, w1.w);
        *reinterpret_cast<uint4*>(&Ws[r * XSTR + c8 * 8]) =
            make_uint4(*(uint32_t*)&g0, *(uint32_t*)&g1,
                       *(uint32_t*)&g2, *(uint32_t*)&g3);

        float4 v0 = make_float4(0.f, 0.f, 0.f, 0.f), v1 = v0;
        if (node0 + r < NNODES) {
            const float4* xr = reinterpret_cast<const float4*>(
                x + (size_t)(node0 + r) * FEAT);
            v0 = __ldg(&xr[2 * c8]);
            v1 = __ldg(&xr[2 * c8 + 1]);
        }
        __half2 h0 = __floats2half2_rn(v0.x, v0.y);
        __half2 h1 = __floats2half2_rn(v0.z, v0.w);
        __half2 h2 = __floats2half2_rn(v1.x, v1.y);
        __half2 h3 = __floats2half2_rn(v1.z, v1.w);
        *reinterpret_cast<uint4*>(&Xs[r * XSTR + c8 * 8]) =
            make_uint4(*(uint32_t*)&h0, *(uint32_t*)&h1,
                       *(uint32_t*)&h2, *(uint32_t*)&h3);
    }
    __syncthreads();

    const int wid  = t >> 5;
    const int lane = t & 31;
    const int gi   = lane >> 2;
    const int q    = lane & 3;
    const int r0   = wid * 16 + gi;

    float d[16][4];
#pragma unroll
    for (int nt = 0; nt < 16; nt++)
#pragma unroll
        for (int j = 0; j < 4; j++) d[nt][j] = 0.f;

#pragma unroll
    for (int ks = 0; ks < 8; ks++) {
        const int kbase = ks * 16 + q * 2;
        uint32_t a0 = *(const uint32_t*)&Xs[r0 * XSTR + kbase];
        uint32_t a1 = *(const uint32_t*)&Xs[(r0 + 8) * XSTR + kbase];
        uint32_t a2 = *(const uint32_t*)&Xs[r0 * XSTR + kbase + 8];
        uint32_t a3 = *(const uint32_t*)&Xs[(r0 + 8) * XSTR + kbase + 8];
#pragma unroll
        for (int nt = 0; nt < 16; nt++) {
            int n = nt * 8 + gi;
            uint32_t b0 = *(const uint32_t*)&Ws[n * XSTR + kbase];
            uint32_t b1 = *(const uint32_t*)&Ws[n * XSTR + kbase + 8];
            hmma16816(d[nt], a0, a1, a2, a3, b0, b1);
        }
    }

    __syncthreads();
#pragma unroll
    for (int nt = 0; nt < 16; nt++) {
        int col = nt * 8 + q * 2;
        __half2 lo = __floats2half2_rn(d[nt][0], d[nt][1]);
        __half2 hi = __floats2half2_rn(d[nt][2], d[nt][3]);
        *reinterpret_cast<__half2*>(&Xs[r0 * XSTR + col])       = lo;
        *reinterpret_cast<__half2*>(&Xs[(r0 + 8) * XSTR + col]) = hi;
    }
    __syncthreads();

#pragma unroll
    for (int i = 0; i < 8; i++) {
        int idx = i * 256 + t;
        int r   = idx >> 4;
        int c8  = idx & 15;
        if (node0 + r < NNODES) {
            *reinterpret_cast<uint4*>(&g_yh[(size_t)(node0 + r) * FEAT + c8 * 8]) =
                *reinterpret_cast<const uint4*>(&Xs[r * XSTR + c8 * 8]);
        }
    }
}

// ---------------------------------------------------------------------------
// K2: pull-gather v4 — straight-line, 16-edge batches.
// One warp per node. Half-warp h handles quads {8i+4h .. 8i+4h+3}, i=0,1,
// FULLY unrolled; absent edges become predicated LDGs into zero-initialized
// registers (fp16 +0 is exact additive identity -> no tail path, no
// divergent branches). 8 independent LDG.128 per lane, front-batched.
// ---------------------------------------------------------------------------
__global__ void __launch_bounds__(256)
sage_gather(const float* __restrict__ b,
            float* __restrict__ out) {
    int w = (blockIdx.x * blockDim.x + threadIdx.x) >> 5;
    if (w >= NNODES) return;
    const int lane = threadIdx.x & 31;
    const int half = lane >> 4;
    const int c    = lane & 15;
    const int l16  = lane & 15;

    const int deg = g_cnt[(size_t)w * CNTPAD];
    const int* idxp = &g_csr[(size_t)w * CSTRIDE];
    const char* ybase = reinterpret_cast<const char*>(g_yh);

    float acc[8] = {0.f, 0.f, 0.f, 0.f, 0.f, 0.f, 0.f, 0.f};

    for (int base = 0; base < deg; base += 16) {
        const int cnt = min(16, deg - base);
        int idx = 0;
        if (l16 < cnt) idx = __ldg(&idxp[base + l16]);   // lanes 16-31 mirror 0-15

#pragma unroll
        for (int i = 0; i < 2; i++) {
            const int e0 = 8 * i + 4 * half;
            const int s0 = __shfl_sync(0xffffffffu, idx, e0 + 0);
            const int s1 = __shfl_sync(0xffffffffu, idx, e0 + 1);
            const int s2 = __shfl_sync(0xffffffffu, idx, e0 + 2);
            const int s3 = __shfl_sync(0xffffffffu, idx, e0 + 3);

            uint4 v0 = make_uint4(0u, 0u, 0u, 0u);
            uint4 v1 = v0, v2 = v0, v3 = v0;
            if (e0 + 0 < cnt) v0 = __ldg(reinterpret_cast<const uint4*>(
                                     ybase + ((unsigned)s0 << 8)) + c);
            if (e0 + 1 < cnt) v1 = __ldg(reinterpret_cast<const uint4*>(
                                     ybase + ((unsigned)s1 << 8)) + c);
            if (e0 + 2 < cnt) v2 = __ldg(reinterpret_cast<const uint4*>(
                                     ybase + ((unsigned)s2 << 8)) + c);
            if (e0 + 3 < cnt) v3 = __ldg(reinterpret_cast<const uint4*>(
                                     ybase + ((unsigned)s3 << 8)) + c);

            const __half2* h0 = reinterpret_cast<const __half2*>(&v0);
            const __half2* h1 = reinterpret_cast<const __half2*>(&v1);
            const __half2* h2 = reinterpret_cast<const __half2*>(&v2);
            const __half2* h3 = reinterpret_cast<const __half2*>(&v3);
#pragma unroll
            for (int qq = 0; qq < 4; qq++) {
                __half2 ta = __hadd2(h0[qq], h1[qq]);
                __half2 tb = __hadd2(h2[qq], h3[qq]);
                __half2 s  = __hadd2(ta, tb);
                float2 f = __half22float2(s);
                acc[2 * qq]     += f.x;
                acc[2 * qq + 1] += f.y;
            }
        }
    }

#pragma unroll
    for (int qq = 0; qq < 8; qq++)
        acc[qq] += __shfl_xor_sync(0xffffffffu, acc[qq], 16);

    if (half == 0) {
        float inv = 1.0f / ((float)deg + 1e-6f);
        const float4* b4 = reinterpret_cast<const float4*>(b);
        float4 b0 = __ldg(&b4[2 * c]);
        float4 b1 = __ldg(&b4[2 * c + 1]);
        float4 o0, o1;
        o0.x = acc[0] * inv + b0.x;  o0.y = acc[1] * inv + b0.y;
        o0.z = acc[2] * inv + b0.z;  o0.w = acc[3] * inv + b0.w;
        o1.x = acc[4] * inv + b1.x;  o1.y = acc[5] * inv + b1.y;
        o1.z = acc[6] * inv + b1.z;  o1.w = acc[7] * inv + b1.w;
        float4* o = reinterpret_cast<float4*>(out + (size_t)w * FEAT);
        o[2 * c]     = o0;
        o[2 * c + 1] = o1;
    }
}

// ---------------------------------------------------------------------------
// Launch
// ---------------------------------------------------------------------------
extern "C" void kernel_launch(void* const* d_in, const int* in_sizes, int n_in,
                              void* d_out, int out_size) {
    const float* x   = (const float*)d_in[0];
    const int*   row = (const int*)  d_in[1];
    const int*   col = (const int*)  d_in[2];
    const float* W   = (const float*)d_in[3];
    const float* b   = (const float*)d_in[4];
    float*       out = (float*)d_out;

    const int E = in_sizes[1];
    const int eblocks = (E + 255) / 256;

    cudaFuncSetAttribute(sage_fused,
                         cudaFuncAttributeMaxDynamicSharedMemorySize,
                         SM_GEMM_TOT);

    // zero the padded counters (graph-capturable async memset)
    void* cnt_ptr = nullptr;
    cudaGetSymbolAddress(&cnt_ptr, g_cnt);
    cudaMemsetAsync(cnt_ptr, 0, (size_t)NNODES * CNTPAD * sizeof(int));

    sage_fused<<<NTILES + eblocks, 256, SM_GEMM_TOT>>>(x, W, row, col, E);
    sage_gather<<<(NNODES + 7) / 8, 256>>>(b, out);
}

// round 12
// speedup vs baseline: 1.5432x; 1.5432x over previous
#include <cuda_runtime.h>
#include <cuda_fp16.h>
#include <cstdint>

#define NNODES  40000
#define FEAT    128
#define CSTRIDE 64                       // padded CSR row stride
#define CNTPAD  8                        // counter stride (ints) -> 1 per 32B sector
#define NTILES  ((NNODES + 127) / 128)   // 313 GEMM tiles
#define XSTR    136                      // smem row stride in halves (+8 pad)

// ---------------------------------------------------------------------------
// Scratch (device globals — no allocations allowed)
// ---------------------------------------------------------------------------
__device__ __half g_yh[(size_t)NNODES * FEAT];       // y = x @ W^T  fp16
__device__ int    g_cnt[(size_t)NNODES * CNTPAD];    // padded degree counters
__device__ int    g_csr[(size_t)NNODES * CSTRIDE];   // padded CSR

__device__ __forceinline__ void hmma16816(float d[4],
                                          uint32_t a0, uint32_t a1,
                                          uint32_t a2, uint32_t a3,
                                          uint32_t b0, uint32_t b1) {
    asm volatile(
        "mma.sync.aligned.m16n8k16.row.col.f32.f16.f16.f32 "
        "{%0,%1,%2,%3}, {%4,%5,%6,%7}, {%8,%9}, {%0,%1,%2,%3};"
        : "+f"(d[0]), "+f"(d[1]), "+f"(d[2]), "+f"(d[3])
        : "r"(a0), "r"(a1), "r"(a2), "r"(a3), "r"(b0), "r"(b1));
}

// ---------------------------------------------------------------------------
// K1 (fused): blocks [0, NTILES) = HMMA GEMM tile; blocks >= NTILES = build.
// ---------------------------------------------------------------------------
#define SM_XS 0
#define SM_WS (128 * XSTR * 2)
#define SM_GEMM_TOT (2 * 128 * XSTR * 2)

__global__ void __launch_bounds__(256)
sage_fused(const float* __restrict__ x,
           const float* __restrict__ W,
           const int*   __restrict__ row,
           const int*   __restrict__ col, int E) {
    if (blockIdx.x >= NTILES) {
        // ----------------- CSR build branch -----------------
        int e = (blockIdx.x - NTILES) * 256 + threadIdx.x;
        if (e >= E) return;
        int r = __ldg(&row[e]);
        int c = __ldg(&col[e]);
        int pos = atomicAdd(&g_cnt[(size_t)r * CNTPAD], 1);
        if (pos < CSTRIDE)
            g_csr[(size_t)r * CSTRIDE + pos] = c;
        return;
    }

    // ----------------- GEMM branch -----------------
    extern __shared__ char smem[];
    __half* Xs = reinterpret_cast<__half*>(smem + SM_XS);
    __half* Ws = reinterpret_cast<__half*>(smem + SM_WS);

    const int t = threadIdx.x;
    const int node0 = blockIdx.x * 128;

    const float4* W4 = reinterpret_cast<const float4*>(W);
#pragma unroll
    for (int i = 0; i < 8; i++) {
        int idx = i * 256 + t;
        int r   = idx >> 4;
        int c8  = idx & 15;

        float4 w0 = __ldg(&W4[r * 32 + 2 * c8]);
        float4 w1 = __ldg(&W4[r * 32 + 2 * c8 + 1]);
        __half2 g0 = __floats2half2_rn(w0.x, w0.y);
        __half2 g1 = __floats2half2_rn(w0.z, w0.w);
        __half2 g2 = __floats2half2_rn(w1.x, w1.y);
        __half2 g3 = __floats2half2_rn(w1.z, w1.w);
        *reinterpret_cast<uint4*>(&Ws[r * XSTR + c8 * 8]) =
            make_uint4(*(uint32_t*)&g0, *(uint32_t*)&g1,
                       *(uint32_t*)&g2, *(uint32_t*)&g3);

        float4 v0 = make_float4(0.f, 0.f, 0.f, 0.f), v1 = v0;
        if (node0 + r < NNODES) {
            const float4* xr = reinterpret_cast<const float4*>(
                x + (size_t)(node0 + r) * FEAT);
            v0 = __ldg(&xr[2 * c8]);
            v1 = __ldg(&xr[2 * c8 + 1]);
        }
        __half2 h0 = __floats2half2_rn(v0.x, v0.y);
        __half2 h1 = __floats2half2_rn(v0.z, v0.w);
        __half2 h2 = __floats2half2_rn(v1.x, v1.y);
        __half2 h3 = __floats2half2_rn(v1.z, v1.w);
        *reinterpret_cast<uint4*>(&Xs[r * XSTR + c8 * 8]) =
            make_uint4(*(uint32_t*)&h0, *(uint32_t*)&h1,
                       *(uint32_t*)&h2, *(uint32_t*)&h3);
    }
    __syncthreads();

    const int wid  = t >> 5;
    const int lane = t & 31;
    const int gi   = lane >> 2;
    const int q    = lane & 3;
    const int r0   = wid * 16 + gi;

    float d[16][4];
#pragma unroll
    for (int nt = 0; nt < 16; nt++)
#pragma unroll
        for (int j = 0; j < 4; j++) d[nt][j] = 0.f;

#pragma unroll
    for (int ks = 0; ks < 8; ks++) {
        const int kbase = ks * 16 + q * 2;
        uint32_t a0 = *(const uint32_t*)&Xs[r0 * XSTR + kbase];
        uint32_t a1 = *(const uint32_t*)&Xs[(r0 + 8) * XSTR + kbase];
        uint32_t a2 = *(const uint32_t*)&Xs[r0 * XSTR + kbase + 8];
        uint32_t a3 = *(const uint32_t*)&Xs[(r0 + 8) * XSTR + kbase + 8];
#pragma unroll
        for (int nt = 0; nt < 16; nt++) {
            int n = nt * 8 + gi;
            uint32_t b0 = *(const uint32_t*)&Ws[n * XSTR + kbase];
            uint32_t b1 = *(const uint32_t*)&Ws[n * XSTR + kbase + 8];
            hmma16816(d[nt], a0, a1, a2, a3, b0, b1);
        }
    }

    __syncthreads();
#pragma unroll
    for (int nt = 0; nt < 16; nt++) {
        int col = nt * 8 + q * 2;
        __half2 lo = __floats2half2_rn(d[nt][0], d[nt][1]);
        __half2 hi = __floats2half2_rn(d[nt][2], d[nt][3]);
        *reinterpret_cast<__half2*>(&Xs[r0 * XSTR + col])       = lo;
        *reinterpret_cast<__half2*>(&Xs[(r0 + 8) * XSTR + col]) = hi;
    }
    __syncthreads();

#pragma unroll
    for (int i = 0; i < 8; i++) {
        int idx = i * 256 + t;
        int r   = idx >> 4;
        int c8  = idx & 15;
        if (node0 + r < NNODES) {
            *reinterpret_cast<uint4*>(&g_yh[(size_t)(node0 + r) * FEAT + c8 * 8]) =
                *reinterpret_cast<const uint4*>(&Xs[r * XSTR + c8 * 8]);
        }
    }
}

// ---------------------------------------------------------------------------
// K2: pull-gather — R8 pair structure (measured best: 21.1 us, 32 regs,
// occ 80%), with the divergent tail body replaced by predicated zero-fill
// loads (fp16 +0 = exact additive identity). Uniform trip count, no
// divergent branches, ~2 loads in flight, low register pressure.
// ---------------------------------------------------------------------------
__global__ void __launch_bounds__(256)
sage_gather(const float* __restrict__ b,
            float* __restrict__ out) {
    int w = (blockIdx.x * blockDim.x + threadIdx.x) >> 5;
    if (w >= NNODES) return;
    const int lane = threadIdx.x & 31;
    const int half = lane >> 4;
    const int c    = lane & 15;

    const int deg = g_cnt[(size_t)w * CNTPAD];
    const int* idxp = &g_csr[(size_t)w * CSTRIDE];
    const char* ybase = reinterpret_cast<const char*>(g_yh);

    float acc[8] = {0.f, 0.f, 0.f, 0.f, 0.f, 0.f, 0.f, 0.f};

    for (int base = 0; base < deg; base += 32) {
        const int cnt = min(32, deg - base);
        int idx = (lane < cnt) ? __ldg(&idxp[base + lane]) : 0;
        const int iters = (cnt + 3) >> 2;            // uniform across warp
#pragma unroll 4
        for (int i = 0; i < iters; i++) {
            const int e0 = 4 * i + 2 * half;
            const int s0 = __shfl_sync(0xffffffffu, idx, e0 & 31);
            const int s1 = __shfl_sync(0xffffffffu, idx, (e0 + 1) & 31);

            uint4 va = make_uint4(0u, 0u, 0u, 0u);
            uint4 vb = va;
            if (e0 < cnt)     va = __ldg(reinterpret_cast<const uint4*>(
                                      ybase + ((unsigned)s0 << 8)) + c);
            if (e0 + 1 < cnt) vb = __ldg(reinterpret_cast<const uint4*>(
                                      ybase + ((unsigned)s1 << 8)) + c);

            const __half2* ha = reinterpret_cast<const __half2*>(&va);
            const __half2* hb = reinterpret_cast<const __half2*>(&vb);
#pragma unroll
            for (int qq = 0; qq < 4; qq++) {
                __half2 s = __hadd2(ha[qq], hb[qq]);
                float2 f = __half22float2(s);
                acc[2 * qq]     += f.x;
                acc[2 * qq + 1] += f.y;
            }
        }
    }

#pragma unroll
    for (int qq = 0; qq < 8; qq++)
        acc[qq] += __shfl_xor_sync(0xffffffffu, acc[qq], 16);

    if (half == 0) {
        float inv = 1.0f / ((float)deg + 1e-6f);
        const float4* b4 = reinterpret_cast<const float4*>(b);
        float4 b0 = __ldg(&b4[2 * c]);
        float4 b1 = __ldg(&b4[2 * c + 1]);
        float4 o0, o1;
        o0.x = acc[0] * inv + b0.x;  o0.y = acc[1] * inv + b0.y;
        o0.z = acc[2] * inv + b0.z;  o0.w = acc[3] * inv + b0.w;
        o1.x = acc[4] * inv + b1.x;  o1.y = acc[5] * inv + b1.y;
        o1.z = acc[6] * inv + b1.z;  o1.w = acc[7] * inv + b1.w;
        float4* o = reinterpret_cast<float4*>(out + (size_t)w * FEAT);
        o[2 * c]     = o0;
        o[2 * c + 1] = o1;
    }
}

// ---------------------------------------------------------------------------
// Launch
// ---------------------------------------------------------------------------
extern "C" void kernel_launch(void* const* d_in, const int* in_sizes, int n_in,
                              void* d_out, int out_size) {
    const float* x   = (const float*)d_in[0];
    const int*   row = (const int*)  d_in[1];
    const int*   col = (const int*)  d_in[2];
    const float* W   = (const float*)d_in[3];
    const float* b   = (const float*)d_in[4];
    float*       out = (float*)d_out;

    const int E = in_sizes[1];
    const int eblocks = (E + 255) / 256;

    cudaFuncSetAttribute(sage_fused,
                         cudaFuncAttributeMaxDynamicSharedMemorySize,
                         SM_GEMM_TOT);

    // zero the padded counters (graph-capturable async memset)
    void* cnt_ptr = nullptr;
    cudaGetSymbolAddress(&cnt_ptr, g_cnt);
    cudaMemsetAsync(cnt_ptr, 0, (size_t)NNODES * CNTPAD * sizeof(int));

    sage_fused<<<NTILES + eblocks, 256, SM_GEMM_TOT>>>(x, W, row, col, E);
    sage_gather<<<(NNODES + 7) / 8, 256>>>(b, out);
}

// round 13
// speedup vs baseline: 1.6247x; 1.0528x over previous
#include <cuda_runtime.h>
#include <cuda_fp16.h>
#include <cstdint>

#define NNODES  40000
#define FEAT    128
#define CSTRIDE 64                       // padded CSR row stride
#define CNTPAD  8                        // counter stride (ints) -> 1 per 32B sector
#define NTILES  ((NNODES + 127) / 128)   // 313 GEMM tiles
#define XSTR    136                      // smem row stride in halves (+8 pad)

// ---------------------------------------------------------------------------
// Scratch (device globals — no allocations allowed)
// ---------------------------------------------------------------------------
__device__ __half g_yh[(size_t)NNODES * FEAT];       // y = x @ W^T  fp16
__device__ int    g_cnt[(size_t)NNODES * CNTPAD];    // padded degree counters
__device__ int    g_csr[(size_t)NNODES * CSTRIDE];   // padded CSR

__device__ __forceinline__ void hmma16816(float d[4],
                                          uint32_t a0, uint32_t a1,
                                          uint32_t a2, uint32_t a3,
                                          uint32_t b0, uint32_t b1) {
    asm volatile(
        "mma.sync.aligned.m16n8k16.row.col.f32.f16.f16.f32 "
        "{%0,%1,%2,%3}, {%4,%5,%6,%7}, {%8,%9}, {%0,%1,%2,%3};"
        : "+f"(d[0]), "+f"(d[1]), "+f"(d[2]), "+f"(d[3])
        : "r"(a0), "r"(a1), "r"(a2), "r"(a3), "r"(b0), "r"(b1));
}

// ---------------------------------------------------------------------------
// K1 (fused): blocks [0, NTILES) = HMMA GEMM tile; blocks >= NTILES = build.
// ---------------------------------------------------------------------------
#define SM_XS 0
#define SM_WS (128 * XSTR * 2)
#define SM_GEMM_TOT (2 * 128 * XSTR * 2)

__global__ void __launch_bounds__(256)
sage_fused(const float* __restrict__ x,
           const float* __restrict__ W,
           const int*   __restrict__ row,
           const int*   __restrict__ col, int E) {
    if (blockIdx.x >= NTILES) {
        // ----------------- CSR build branch -----------------
        int e = (blockIdx.x - NTILES) * 256 + threadIdx.x;
        if (e >= E) return;
        int r = __ldg(&row[e]);
        int c = __ldg(&col[e]);
        int pos = atomicAdd(&g_cnt[(size_t)r * CNTPAD], 1);
        if (pos < CSTRIDE)
            g_csr[(size_t)r * CSTRIDE + pos] = c;
        return;
    }

    // ----------------- GEMM branch -----------------
    extern __shared__ char smem[];
    __half* Xs = reinterpret_cast<__half*>(smem + SM_XS);
    __half* Ws = reinterpret_cast<__half*>(smem + SM_WS);

    const int t = threadIdx.x;
    const int node0 = blockIdx.x * 128;

    const float4* W4 = reinterpret_cast<const float4*>(W);
#pragma unroll
    for (int i = 0; i < 8; i++) {
        int idx = i * 256 + t;
        int r   = idx >> 4;
        int c8  = idx & 15;

        float4 w0 = __ldg(&W4[r * 32 + 2 * c8]);
        float4 w1 = __ldg(&W4[r * 32 + 2 * c8 + 1]);
        __half2 g0 = __floats2half2_rn(w0.x, w0.y);
        __half2 g1 = __floats2half2_rn(w0.z, w0.w);
        __half2 g2 = __floats2half2_rn(w1.x, w1.y);
        __half2 g3 = __floats2half2_rn(w1.z, w1.w);
        *reinterpret_cast<uint4*>(&Ws[r * XSTR + c8 * 8]) =
            make_uint4(*(uint32_t*)&g0, *(uint32_t*)&g1,
                       *(uint32_t*)&g2, *(uint32_t*)&g3);

        float4 v0 = make_float4(0.f, 0.f, 0.f, 0.f), v1 = v0;
        if (node0 + r < NNODES) {
            const float4* xr = reinterpret_cast<const float4*>(
                x + (size_t)(node0 + r) * FEAT);
            v0 = __ldg(&xr[2 * c8]);
            v1 = __ldg(&xr[2 * c8 + 1]);
        }
        __half2 h0 = __floats2half2_rn(v0.x, v0.y);
        __half2 h1 = __floats2half2_rn(v0.z, v0.w);
        __half2 h2 = __floats2half2_rn(v1.x, v1.y);
        __half2 h3 = __floats2half2_rn(v1.z, v1.w);
        *reinterpret_cast<uint4*>(&Xs[r * XSTR + c8 * 8]) =
            make_uint4(*(uint32_t*)&h0, *(uint32_t*)&h1,
                       *(uint32_t*)&h2, *(uint32_t*)&h3);
    }
    __syncthreads();

    const int wid  = t >> 5;
    const int lane = t & 31;
    const int gi   = lane >> 2;
    const int q    = lane & 3;
    const int r0   = wid * 16 + gi;

    float d[16][4];
#pragma unroll
    for (int nt = 0; nt < 16; nt++)
#pragma unroll
        for (int j = 0; j < 4; j++) d[nt][j] = 0.f;

#pragma unroll
    for (int ks = 0; ks < 8; ks++) {
        const int kbase = ks * 16 + q * 2;
        uint32_t a0 = *(const uint32_t*)&Xs[r0 * XSTR + kbase];
        uint32_t a1 = *(const uint32_t*)&Xs[(r0 + 8) * XSTR + kbase];
        uint32_t a2 = *(const uint32_t*)&Xs[r0 * XSTR + kbase + 8];
        uint32_t a3 = *(const uint32_t*)&Xs[(r0 + 8) * XSTR + kbase + 8];
#pragma unroll
        for (int nt = 0; nt < 16; nt++) {
            int n = nt * 8 + gi;
            uint32_t b0 = *(const uint32_t*)&Ws[n * XSTR + kbase];
            uint32_t b1 = *(const uint32_t*)&Ws[n * XSTR + kbase + 8];
            hmma16816(d[nt], a0, a1, a2, a3, b0, b1);
        }
    }

    __syncthreads();
#pragma unroll
    for (int nt = 0; nt < 16; nt++) {
        int col = nt * 8 + q * 2;
        __half2 lo = __floats2half2_rn(d[nt][0], d[nt][1]);
        __half2 hi = __floats2half2_rn(d[nt][2], d[nt][3]);
        *reinterpret_cast<__half2*>(&Xs[r0 * XSTR + col])       = lo;
        *reinterpret_cast<__half2*>(&Xs[(r0 + 8) * XSTR + col]) = hi;
    }
    __syncthreads();

#pragma unroll
    for (int i = 0; i < 8; i++) {
        int idx = i * 256 + t;
        int r   = idx >> 4;
        int c8  = idx & 15;
        if (node0 + r < NNODES) {
            *reinterpret_cast<uint4*>(&g_yh[(size_t)(node0 + r) * FEAT + c8 * 8]) =
                *reinterpret_cast<const uint4*>(&Xs[r * XSTR + c8 * 8]);
        }
    }
}

// ---------------------------------------------------------------------------
// K2: pull-gather v6 — R8 skeleton (divergent tail, 32 regs, 80% occ) with
// FULL fp16 accumulation: per pair = 8 HADD2 total, no cvt/fadd in the loop.
// fp32 conversion happens once after the loop, before the cross-half reduce.
// ---------------------------------------------------------------------------
__global__ void __launch_bounds__(256)
sage_gather(const float* __restrict__ b,
            float* __restrict__ out) {
    int w = (blockIdx.x * blockDim.x + threadIdx.x) >> 5;
    if (w >= NNODES) return;
    const int lane = threadIdx.x & 31;
    const int half = lane >> 4;
    const int c    = lane & 15;

    const int deg = g_cnt[(size_t)w * CNTPAD];
    const int* idxp = &g_csr[(size_t)w * CSTRIDE];
    const char* ybase = reinterpret_cast<const char*>(g_yh);

    __half2 hacc[4];
#pragma unroll
    for (int qq = 0; qq < 4; qq++) hacc[qq] = __float2half2_rn(0.f);

    for (int base = 0; base < deg; base += 32) {
        const int cnt = min(32, deg - base);
        int idx = (lane < cnt) ? __ldg(&idxp[base + lane]) : 0;
        const int iters = (cnt + 3) >> 2;            // uniform across warp
#pragma unroll 4
        for (int i = 0; i < iters; i++) {
            const int e0 = 4 * i + 2 * half;
            const int s0 = __shfl_sync(0xffffffffu, idx, e0 & 31);
            const int s1 = __shfl_sync(0xffffffffu, idx, (e0 + 1) & 31);
            if (e0 + 1 < cnt) {
                uint4 va = __ldg(reinterpret_cast<const uint4*>(
                    ybase + ((unsigned)s0 << 8)) + c);
                uint4 vb = __ldg(reinterpret_cast<const uint4*>(
                    ybase + ((unsigned)s1 << 8)) + c);
                const __half2* ha = reinterpret_cast<const __half2*>(&va);
                const __half2* hb = reinterpret_cast<const __half2*>(&vb);
#pragma unroll
                for (int qq = 0; qq < 4; qq++)
                    hacc[qq] = __hadd2(hacc[qq], __hadd2(ha[qq], hb[qq]));
            } else if (e0 < cnt) {
                uint4 va = __ldg(reinterpret_cast<const uint4*>(
                    ybase + ((unsigned)s0 << 8)) + c);
                const __half2* ha = reinterpret_cast<const __half2*>(&va);
#pragma unroll
                for (int qq = 0; qq < 4; qq++)
                    hacc[qq] = __hadd2(hacc[qq], ha[qq]);
            }
        }
    }

    // fp32 conversion + cross-half reduce
    float acc[8];
#pragma unroll
    for (int qq = 0; qq < 4; qq++) {
        float2 f = __half22float2(hacc[qq]);
        acc[2 * qq]     = f.x;
        acc[2 * qq + 1] = f.y;
    }
#pragma unroll
    for (int qq = 0; qq < 8; qq++)
        acc[qq] += __shfl_xor_sync(0xffffffffu, acc[qq], 16);

    if (half == 0) {
        float inv = 1.0f / ((float)deg + 1e-6f);
        const float4* b4 = reinterpret_cast<const float4*>(b);
        float4 b0 = __ldg(&b4[2 * c]);
        float4 b1 = __ldg(&b4[2 * c + 1]);
        float4 o0, o1;
        o0.x = acc[0] * inv + b0.x;  o0.y = acc[1] * inv + b0.y;
        o0.z = acc[2] * inv + b0.z;  o0.w = acc[3] * inv + b0.w;
        o1.x = acc[4] * inv + b1.x;  o1.y = acc[5] * inv + b1.y;
        o1.z = acc[6] * inv + b1.z;  o1.w = acc[7] * inv + b1.w;
        float4* o = reinterpret_cast<float4*>(out + (size_t)w * FEAT);
        o[2 * c]     = o0;
        o[2 * c + 1] = o1;
    }
}

// ---------------------------------------------------------------------------
// Launch
// ---------------------------------------------------------------------------
extern "C" void kernel_launch(void* const* d_in, const int* in_sizes, int n_in,
                              void* d_out, int out_size) {
    const float* x   = (const float*)d_in[0];
    const int*   row = (const int*)  d_in[1];
    const int*   col = (const int*)  d_in[2];
    const float* W   = (const float*)d_in[3];
    const float* b   = (const float*)d_in[4];
    float*       out = (float*)d_out;

    const int E = in_sizes[1];
    const int eblocks = (E + 255) / 256;

    cudaFuncSetAttribute(sage_fused,
                         cudaFuncAttributeMaxDynamicSharedMemorySize,
                         SM_GEMM_TOT);

    // zero the padded counters (graph-capturable async memset)
    void* cnt_ptr = nullptr;
    cudaGetSymbolAddress(&cnt_ptr, g_cnt);
    cudaMemsetAsync(cnt_ptr, 0, (size_t)NNODES * CNTPAD * sizeof(int));

    sage_fused<<<NTILES + eblocks, 256, SM_GEMM_TOT>>>(x, W, row, col, E);
    sage_gather<<<(NNODES + 7) / 8, 256>>>(b, out);
}